// round 5
// baseline (speedup 1.0000x reference)
#include <cuda_runtime.h>
#include <cstdint>

// ---------------- problem constants ----------------
#define D_DIM  512
#define HID    513
#define HIDP   576            // 6 * 96
#define P_CTX  8192
#define KTEST  2048
#define LDEPTH 8
#define HIDP2  (HIDP*HIDP)

#define TM     96             // tile M = N = 96
#define CH     32             // K per chunk
#define SST    100            // smem row stride (words)
#define NT6    6
#define GSPL   4              // split-K for 576-deep GEMMs  -> 36*4 = 144 CTAs
#define SSPL   7              // split-K for syrk            -> 21*7 = 147 CTAs
#define NPAIR  21             // upper-tri 96-tile pairs (6x6)
#define TILE_ELEMS (TM*TM)    // 9216
#define SMEM_SZ (4*CH*SST*4)  // 51200 B

// ---------------- scratch ----------------
__device__ float g_Part[NPAIR*SSPL*TILE_ELEMS];   // >= 36*GSPL*9216 too
__device__ unsigned int g_cnt[40];                // zero-init counters
__device__ float g_S  [HIDP2];
__device__ float g_Wxa[HIDP2];
__device__ float g_WqT[HIDP2];
__device__ float g_WkT[HIDP2];
__device__ float g_WvP[HIDP2];
__device__ float g_F  [HIDP2];
__device__ float g_G  [HIDP2];
__device__ float g_T  [HIDP2];
__device__ float g_T2 [HIDP2];
__device__ float g_A  [LDEPTH*HIDP2];
__device__ float g_u  [2*HID];
__device__ float g_d  [D_DIM];

// ================= fp32 GEMM, 96x96 tile, split-K, last-CTA reduce =========
// acc(m,n) = sum_k A[m,k]*B[n,k]    (both row-major, K contiguous)
// mode 0: C = alpha*acc      mode 1: C = Dm - acc
// mode 2: syrk of aug=[X|y]: blockIdx.x = pair, symmetric write into C (=S)
__global__ __launch_bounds__(256) void gemm96(
    const float* __restrict__ A, int lda,
    const float* __restrict__ B, int ldb,
    const float* __restrict__ yv,
    float* __restrict__ C, const float* __restrict__ Dm,
    float alpha, int mode)
{
    extern __shared__ float sm[];
    __shared__ int slast;
    const int tid = threadIdx.x;
    const int tx = tid & 15, ty = tid >> 4;

    int bm, bn, tileId, nsplit, kst, nch;
    const int s = blockIdx.z;
    if (mode == 2) {
        int q = blockIdx.x, ti = 0, rem = q;
        while (rem >= NT6 - ti) { rem -= NT6 - ti; ti++; }
        bm = ti * TM; bn = (ti + rem) * TM; tileId = q;
        nsplit = SSPL;
        const int stch = (s < 4) ? 37 * s : 148 + 36 * (s - 4);
        nch = (s < 4) ? 37 : 36;             // 4*37 + 3*36 = 256 chunks = 8192
        kst = stch * CH;
    } else {
        bm = blockIdx.y * TM; bn = blockIdx.x * TM;
        tileId = blockIdx.y * NT6 + blockIdx.x;
        nsplit = GSPL;
        kst = (s < 2) ? 160 * s : 320 + 128 * (s - 2);   // 160+160+128+128=576
        nch = (s < 2) ? 5 : 4;
    }

    float* Ab0 = sm;
    float* Ab1 = sm + CH * SST;
    float* Bb0 = sm + 2 * CH * SST;
    float* Bb1 = sm + 3 * CH * SST;

    float4 va[3], vb[3];

    auto aug4 = [&](const float* X, int p, int c0) -> float4 {
        if (c0 < D_DIM) return *(const float4*)(X + (size_t)p * D_DIM + c0);
        float4 z = {0.f, 0.f, 0.f, 0.f};
        if (c0 == D_DIM) z.x = yv[p];
        return z;
    };

    auto ldg_chunk = [&](int ch) {
        const int k0 = kst + ch * CH;
        if (mode == 2) {
            #pragma unroll
            for (int i = 0; i < 3; i++) {
                const int f = tid + i * 256;
                const int pl = f / 24, seg = f % 24;
                const int p = k0 + pl;
                va[i] = aug4(A, p, bm + seg * 4);
                vb[i] = aug4(A, p, bn + seg * 4);
            }
        } else {
            #pragma unroll
            for (int i = 0; i < 3; i++) {
                const int f = tid + i * 256;
                const int m = f >> 3, seg = f & 7;
                va[i] = *(const float4*)(A + (size_t)(bm + m) * lda + k0 + seg * 4);
                vb[i] = *(const float4*)(B + (size_t)(bn + m) * ldb + k0 + seg * 4);
            }
        }
    };
    auto sts_chunk = [&](int buf) {
        float* Ab = buf ? Ab1 : Ab0;
        float* Bb = buf ? Bb1 : Bb0;
        if (mode == 2) {
            #pragma unroll
            for (int i = 0; i < 3; i++) {
                const int f = tid + i * 256;
                const int pl = f / 24, sg4 = (f % 24) * 4;
                *(float4*)(Ab + pl * SST + sg4) = va[i];
                *(float4*)(Bb + pl * SST + sg4) = vb[i];
            }
        } else {
            #pragma unroll
            for (int i = 0; i < 3; i++) {
                const int f = tid + i * 256;
                const int m = f >> 3, sg4 = (f & 7) * 4;
                Ab[(sg4 + 0) * SST + m] = va[i].x;
                Ab[(sg4 + 1) * SST + m] = va[i].y;
                Ab[(sg4 + 2) * SST + m] = va[i].z;
                Ab[(sg4 + 3) * SST + m] = va[i].w;
                Bb[(sg4 + 0) * SST + m] = vb[i].x;
                Bb[(sg4 + 1) * SST + m] = vb[i].y;
                Bb[(sg4 + 2) * SST + m] = vb[i].z;
                Bb[(sg4 + 3) * SST + m] = vb[i].w;
            }
        }
    };

    float acc[6][6] = {};

    ldg_chunk(0);
    sts_chunk(0);
    __syncthreads();

    for (int ch = 0; ch < nch; ch++) {
        const int buf = ch & 1;
        const bool more = (ch + 1 < nch);
        if (more) ldg_chunk(ch + 1);

        const float* Ab = buf ? Ab1 : Ab0;
        const float* Bb = buf ? Bb1 : Bb0;
        #pragma unroll 4
        for (int k = 0; k < CH; k++) {
            float a[6], b[6];
            const float* ap = Ab + k * SST + ty * 6;
            const float* bp = Bb + k * SST + tx * 6;
            *(float2*)&a[0] = *(const float2*)(ap);
            *(float2*)&a[2] = *(const float2*)(ap + 2);
            *(float2*)&a[4] = *(const float2*)(ap + 4);
            *(float2*)&b[0] = *(const float2*)(bp);
            *(float2*)&b[2] = *(const float2*)(bp + 2);
            *(float2*)&b[4] = *(const float2*)(bp + 4);
            #pragma unroll
            for (int i = 0; i < 6; i++)
                #pragma unroll
                for (int j = 0; j < 6; j++)
                    acc[i][j] += a[i] * b[j];
        }

        if (more) {
            __syncthreads();
            sts_chunk(buf ^ 1);
            __syncthreads();
        }
    }

    // ---- write split partial ----
    {
        float* P = g_Part + ((size_t)tileId * nsplit + s) * TILE_ELEMS;
        #pragma unroll
        for (int i = 0; i < 6; i++) {
            float* row = P + (ty * 6 + i) * TM + tx * 6;
            *(float2*)(row)     = make_float2(acc[i][0], acc[i][1]);
            *(float2*)(row + 2) = make_float2(acc[i][2], acc[i][3]);
            *(float2*)(row + 4) = make_float2(acc[i][4], acc[i][5]);
        }
    }
    __threadfence();
    __syncthreads();
    if (tid == 0) {
        unsigned int t = atomicAdd(&g_cnt[tileId], 1u);
        slast = (t == (unsigned)(nsplit - 1)) ? 1 : 0;
    }
    __syncthreads();
    if (!slast) return;

    // ---- last CTA: deterministic reduce (fixed split order) + epilogue ----
    #pragma unroll 1
    for (int g = 0; g < 9; g++) {
        const int idx = tid * 4 + g * 1024;        // < 9216
        float4 sum = {0.f, 0.f, 0.f, 0.f};
        for (int z = 0; z < nsplit; z++) {
            const float4 v = *(const float4*)(
                g_Part + ((size_t)tileId * nsplit + z) * TILE_ELEMS + idx);
            sum.x += v.x; sum.y += v.y; sum.z += v.z; sum.w += v.w;
        }
        const int m = idx / TM, n = idx % TM;
        const size_t go = (size_t)(bm + m) * HIDP + bn + n;
        if (mode == 0) {
            *(float4*)(C + go) = make_float4(alpha * sum.x, alpha * sum.y,
                                             alpha * sum.z, alpha * sum.w);
        } else if (mode == 1) {
            const float4 d = *(const float4*)(Dm + go);
            *(float4*)(C + go) = make_float4(d.x - sum.x, d.y - sum.y,
                                             d.z - sum.z, d.w - sum.w);
        } else {
            *(float4*)(C + go) = sum;
            C[(size_t)(bn + n + 0) * HIDP + bm + m] = sum.x;   // mirror
            C[(size_t)(bn + n + 1) * HIDP + bm + m] = sum.y;
            C[(size_t)(bn + n + 2) * HIDP + bm + m] = sum.z;
            C[(size_t)(bn + n + 3) * HIDP + bm + m] = sum.w;
        }
    }
    if (tid == 0) g_cnt[tileId] = 0;   // re-arm for next launch / replay
}

// ---------------- merged padded-operand builder ----------------
__global__ void build_ops(const float* __restrict__ Wx, const float* __restrict__ wy,
                          const float* __restrict__ Wq, const float* __restrict__ Wk,
                          const float* __restrict__ Wv,
                          float* __restrict__ Wxa, float* __restrict__ WqT,
                          float* __restrict__ WkT, float* __restrict__ WvP)
{
    const int idx = blockIdx.x * 256 + threadIdx.x;
    if (idx >= HIDP2) return;
    const int r = idx / HIDP, c = idx % HIDP;
    const bool in = (r < HID && c < HID);
    float wxa = 0.f;
    if (r < HID) {
        if (c < D_DIM) wxa = Wx[(size_t)r * D_DIM + c];
        else if (c == D_DIM) wxa = wy[r];
    }
    Wxa[idx] = wxa;
    WqT[idx] = in ? Wq[(size_t)c * HID + r] : 0.f;
    WkT[idx] = in ? Wk[(size_t)c * HID + r] : 0.f;
    WvP[idx] = in ? Wv[(size_t)r * HID + c] : 0.f;
}

// ---------------- vector tail (fp32 exact) ----------------
__global__ void copy_vec(const float* __restrict__ src, float* __restrict__ dst, int n)
{
    int i = blockIdx.x * 256 + threadIdx.x;
    if (i < n) dst[i] = src[i];
}
// uout[j] = uin[j] + sum_i A[i,j]*uin[i]
__global__ void gemv_t_add(const float* __restrict__ A, const float* __restrict__ uin,
                           float* __restrict__ uout)
{
    int j = blockIdx.x * 256 + threadIdx.x;
    if (j >= HID) return;
    float s = uin[j];
    #pragma unroll 8
    for (int i = 0; i < HID; i++) s += A[(size_t)i * HIDP + j] * uin[i];
    uout[j] = s;
}
__global__ void gemv_wx_t(const float* __restrict__ Wx, const float* __restrict__ u,
                          float* __restrict__ d)
{
    int j = blockIdx.x * 256 + threadIdx.x;
    if (j >= D_DIM) return;
    float s = 0.f;
    #pragma unroll 8
    for (int i = 0; i < HID; i++) s += Wx[(size_t)i * D_DIM + j] * u[i];
    d[j] = s;
}
__global__ void out_k(const float* __restrict__ Xs, const float* __restrict__ d,
                      float* __restrict__ out)
{
    int k = blockIdx.x * 8 + (threadIdx.x >> 5);
    int lane = threadIdx.x & 31;
    if (k >= KTEST) return;
    const float* row = Xs + (size_t)k * D_DIM;
    float s = 0.f;
    #pragma unroll 4
    for (int c = lane; c < D_DIM; c += 32) s += row[c] * d[c];
    #pragma unroll
    for (int o = 16; o > 0; o >>= 1) s += __shfl_xor_sync(0xFFFFFFFFu, s, o);
    if (lane == 0) out[k] = s;
}

// ---------------- host orchestration ----------------
static float* sym_addr(const void* sym) {
    void* p = nullptr;
    cudaGetSymbolAddress(&p, sym);
    return (float*)p;
}

extern "C" void kernel_launch(void* const* d_in, const int* in_sizes, int n_in,
                              void* d_out, int out_size)
{
    const float* X  = (const float*)d_in[0];
    const float* y  = (const float*)d_in[1];
    const float* Xs = (const float*)d_in[2];
    const float* Wx = (const float*)d_in[3];
    const float* wy = (const float*)d_in[4];
    const float* wo = (const float*)d_in[5];
    const float* Wk = (const float*)d_in[6];
    const float* Wq = (const float*)d_in[7];
    const float* Wv = (const float*)d_in[8];
    float* out = (float*)d_out;

    float* S   = sym_addr(g_S);
    float* Wxa = sym_addr(g_Wxa);
    float* WqT = sym_addr(g_WqT);
    float* WkT = sym_addr(g_WkT);
    float* WvP = sym_addr(g_WvP);
    float* F   = sym_addr(g_F);
    float* G   = sym_addr(g_G);
    float* T   = sym_addr(g_T);
    float* T2  = sym_addr(g_T2);
    float* A   = sym_addr(g_A);
    float* u   = sym_addr(g_u);
    float* dv  = sym_addr(g_d);

    static int smem_set = 0;
    if (!smem_set) {
        cudaFuncSetAttribute(gemm96, cudaFuncAttributeMaxDynamicSharedMemorySize, SMEM_SZ);
        smem_set = 1;
    }

    const dim3 gG(NT6, NT6, GSPL);     // 144 CTAs
    const dim3 gS(NPAIR, 1, SSPL);     // 147 CTAs
    const int eb = (HIDP2 + 255) / 256;
    const float scale = 1.0f / (LDEPTH * (float)P_CTX);

    // 1) S = aug^T aug (symmetric, split-K, deterministic last-CTA reduce)
    gemm96<<<gS, 256, SMEM_SZ>>>(X, 0, X, 0, y, S, nullptr, 1.f, 2);

    // 2) padded operands (one launch)
    build_ops<<<eb, 256>>>(Wx, wy, Wq, Wk, Wv, Wxa, WqT, WkT, WvP);

    // 3) G0 = Wxa S Wxa^T ; F = Wq^T Wk (= E^T)
    gemm96<<<gG, 256, SMEM_SZ>>>(Wxa, HIDP, S,   HIDP, nullptr, T, nullptr, 1.f, 0);
    gemm96<<<gG, 256, SMEM_SZ>>>(T,   HIDP, Wxa, HIDP, nullptr, G, nullptr, 1.f, 0);
    gemm96<<<gG, 256, SMEM_SZ>>>(WqT, HIDP, WkT, HIDP, nullptr, F, nullptr, 1.f, 0);

    // 4) layers: T = F G^T(=GE transposed); Al = scale Wv T^T; T2 = G - Al G; G = T2 - T2 Al^T
    for (int l = 0; l < LDEPTH; l++) {
        float* Al = A + (size_t)l * HIDP2;
        gemm96<<<gG, 256, SMEM_SZ>>>(F,   HIDP, G,  HIDP, nullptr, T,  nullptr, 1.f,   0);
        gemm96<<<gG, 256, SMEM_SZ>>>(WvP, HIDP, T,  HIDP, nullptr, Al, nullptr, scale, 0);
        gemm96<<<gG, 256, SMEM_SZ>>>(Al,  HIDP, G,  HIDP, nullptr, T2, G,       1.f,   1);
        gemm96<<<gG, 256, SMEM_SZ>>>(T2,  HIDP, Al, HIDP, nullptr, G,  T2,      1.f,   1);
    }

    // 5) u = prod_{l=L-1..0} (I + A_l)^T  w_o
    copy_vec<<<3, 256>>>(wo, u, HID);
    for (int i = 0; i < LDEPTH; i++) {
        const int l = LDEPTH - 1 - i;
        const int cur = i & 1;
        gemv_t_add<<<3, 256>>>(A + (size_t)l * HIDP2, u + cur * HID, u + (cur ^ 1) * HID);
    }

    // 6) d = Wx^T u ; out = X_star d
    gemv_wx_t<<<2, 256>>>(Wx, u, dv);
    out_k<<<KTEST / 8, 256>>>(Xs, dv, out);
}